// round 4
// baseline (speedup 1.0000x reference)
#include <cuda_runtime.h>

#define BB 2
#define SS 2048
#define DM 512
#define HH 8
#define DK 64

// ---------------- scratch (device globals; no allocation) ----------------
__device__ float g_Q[BB * HH * SS * DK];   // [b][h][s][d]
__device__ float g_K[BB * HH * SS * DK];
__device__ float g_V[BB * HH * SS * DK];
__device__ float g_ctx[BB * SS * DM];      // [b*s][h*64+d]
__device__ float g_tab[HH * 4095];         // bias value per (head, delta+2047)

// Exact integer bucketization (bidirectional T5, NUM_BUCKETS=32, MAX_DISTANCE=128).
// Thresholds derived from 8*ln(n/8)/ln(16); exact-integer cases n=16,32,64 verified
// to land on the integral side in the f32 reference computation.
__device__ __forceinline__ int bucket_abs(int n) {
    if (n < 8)  return n;
    if (n < 12) return 8;
    if (n < 16) return 9;
    if (n < 23) return 10;
    if (n < 32) return 11;
    if (n < 46) return 12;
    if (n < 64) return 13;
    if (n < 91) return 14;
    return 15;
}

// ---------------- kernel 1: bias table ----------------
__global__ void bias_tab_kernel(const float* __restrict__ emb) {
    int i = blockIdx.x * blockDim.x + threadIdx.x;
    if (i >= HH * 4095) return;
    int h = i / 4095;
    int didx = i - h * 4095;
    int d = didx - 2047;              // delta = k - q
    int n = d < 0 ? -d : d;
    int bkt = bucket_abs(n) + (d > 0 ? 16 : 0);
    g_tab[h * 4095 + didx] = emb[bkt * HH + h];
}

// ---------------- kernel 2: stream position_bias to output ----------------
__global__ void bias_write_kernel(float* __restrict__ outb) {
    int h = blockIdx.z;
    int q = blockIdx.y;
    int k = (blockIdx.x * 256 + threadIdx.x) * 4;
    const float* t = &g_tab[h * 4095 + (k - q + 2047)];
    float4 v = make_float4(t[0], t[1], t[2], t[3]);
    *(float4*)&outb[((size_t)h * SS + q) * SS + k] = v;
}

// ---------------- kernel 3: fused QKV projection GEMM ----------------
// C[4096, 3*512] = X[4096,512] @ {Wq|Wk|Wv}[512,512]; epilogue writes [b][h][s][d].
__global__ __launch_bounds__(256) void qkv_gemm(const float* __restrict__ Xh,
                                                const float* __restrict__ Wq,
                                                const float* __restrict__ Wk,
                                                const float* __restrict__ Wv) {
    __shared__ float As[16][64];
    __shared__ float Bs[16][64];
    int t = threadIdx.x;
    int tx = t & 15, ty = t >> 4;
    int m0 = blockIdx.x * 64;
    int w = blockIdx.y >> 3;           // 0=Q,1=K,2=V
    int h = blockIdx.y & 7;
    const float* Bm = (w == 0) ? Wq : ((w == 1) ? Wk : Wv);
    float* dst = (w == 0) ? g_Q : ((w == 1) ? g_K : g_V);
    int n0 = h * 64;

    float acc[4][4];
#pragma unroll
    for (int i = 0; i < 4; i++)
#pragma unroll
        for (int j = 0; j < 4; j++) acc[i][j] = 0.f;

    int ar = t >> 2, ac = (t & 3) * 4;
    int br = t >> 4, bc = (t & 15) * 4;

    for (int k0 = 0; k0 < DM; k0 += 16) {
        float4 av = *(const float4*)&Xh[(size_t)(m0 + ar) * DM + k0 + ac];
        As[ac + 0][ar] = av.x;
        As[ac + 1][ar] = av.y;
        As[ac + 2][ar] = av.z;
        As[ac + 3][ar] = av.w;
        *(float4*)&Bs[br][bc] = *(const float4*)&Bm[(size_t)(k0 + br) * (HH * DK) + n0 + bc];
        __syncthreads();
#pragma unroll
        for (int kk = 0; kk < 16; kk++) {
            float4 a = *(const float4*)&As[kk][ty * 4];
            float4 b = *(const float4*)&Bs[kk][tx * 4];
            acc[0][0] += a.x * b.x; acc[0][1] += a.x * b.y; acc[0][2] += a.x * b.z; acc[0][3] += a.x * b.w;
            acc[1][0] += a.y * b.x; acc[1][1] += a.y * b.y; acc[1][2] += a.y * b.z; acc[1][3] += a.y * b.w;
            acc[2][0] += a.z * b.x; acc[2][1] += a.z * b.y; acc[2][2] += a.z * b.z; acc[2][3] += a.z * b.w;
            acc[3][0] += a.w * b.x; acc[3][1] += a.w * b.y; acc[3][2] += a.w * b.z; acc[3][3] += a.w * b.w;
        }
        __syncthreads();
    }

    int b = m0 >> 11;
    int s0 = m0 & 2047;
#pragma unroll
    for (int i = 0; i < 4; i++) {
        int sr = s0 + ty * 4 + i;
        float4 o = make_float4(acc[i][0], acc[i][1], acc[i][2], acc[i][3]);
        *(float4*)&dst[(((size_t)(b * HH + h)) * SS + sr) * DK + tx * 4] = o;
    }
}

// ---------------- kernel 4: flash attention (fp32, online softmax) ----------------
// smem layout (floats): Qs[64*64] | Ks[64*65] (padded) | Vs[64*64] | Ps[64*64] | strip[127]
#define SM_QS 0
#define SM_KS 4096
#define SM_VS (4096 + 64 * 65)
#define SM_PS (SM_VS + 4096)
#define SM_ST (SM_PS + 4096)
#define SM_FLOATS (SM_ST + 128)

__global__ __launch_bounds__(256) void attn_kernel() {
    extern __shared__ float sm[];
    float* Qs = sm + SM_QS;
    float* Ks = sm + SM_KS;      // row stride 65 (conflict-free scalar reads)
    float* Vs = sm + SM_VS;
    float* Ps = sm + SM_PS;
    float* strip = sm + SM_ST;

    int t = threadIdx.x;
    int tx = t & 15, ty = t >> 4;
    int q0 = blockIdx.x * 64;
    int h = blockIdx.y;
    int b = blockIdx.z;
    int ty4 = ty * 4, tx4 = tx * 4;

    const float* Qg = g_Q + ((size_t)(b * HH + h)) * SS * DK;
    const float* Kg = g_K + ((size_t)(b * HH + h)) * SS * DK;
    const float* Vg = g_V + ((size_t)(b * HH + h)) * SS * DK;

    // load Q tile [64][64]
#pragma unroll
    for (int i = 0; i < 4; i++) {
        int lin = t + i * 256;
        int r = lin >> 4, c = (lin & 15) * 4;
        *(float4*)&Qs[r * 64 + c] = *(const float4*)&Qg[(size_t)(q0 + r) * DK + c];
    }

    float m[4], l[4], o[4][4];
#pragma unroll
    for (int i = 0; i < 4; i++) {
        m[i] = -1e30f;
        l[i] = 0.f;
#pragma unroll
        for (int j = 0; j < 4; j++) o[i][j] = 0.f;
    }

    for (int kt = 0; kt < SS / 64; kt++) {
        int k0 = kt * 64;
        // load K (padded stride 65) and V tiles: 64 rows x 16 float4 each
#pragma unroll
        for (int i = 0; i < 4; i++) {
            int lin = t + i * 256;
            int r = lin >> 4, c = (lin & 15) * 4;
            float4 kv = *(const float4*)&Kg[(size_t)(k0 + r) * DK + c];
            Ks[r * 65 + c + 0] = kv.x;
            Ks[r * 65 + c + 1] = kv.y;
            Ks[r * 65 + c + 2] = kv.z;
            Ks[r * 65 + c + 3] = kv.w;
            *(float4*)&Vs[r * 64 + c] = *(const float4*)&Vg[(size_t)(k0 + r) * DK + c];
        }
        if (t < 127) strip[t] = g_tab[h * 4095 + (k0 - q0 - 63 + 2047) + t];
        __syncthreads();

        // S = Q @ K^T  (4q x 4k per thread)
        float s[4][4];
#pragma unroll
        for (int i = 0; i < 4; i++)
#pragma unroll
            for (int j = 0; j < 4; j++) s[i][j] = 0.f;

#pragma unroll 4
        for (int d = 0; d < 64; d++) {
            float qv0 = Qs[(ty4 + 0) * 64 + d];
            float qv1 = Qs[(ty4 + 1) * 64 + d];
            float qv2 = Qs[(ty4 + 2) * 64 + d];
            float qv3 = Qs[(ty4 + 3) * 64 + d];
            float kv0 = Ks[(tx4 + 0) * 65 + d];
            float kv1 = Ks[(tx4 + 1) * 65 + d];
            float kv2 = Ks[(tx4 + 2) * 65 + d];
            float kv3 = Ks[(tx4 + 3) * 65 + d];
            s[0][0] += qv0 * kv0; s[0][1] += qv0 * kv1; s[0][2] += qv0 * kv2; s[0][3] += qv0 * kv3;
            s[1][0] += qv1 * kv0; s[1][1] += qv1 * kv1; s[1][2] += qv1 * kv2; s[1][3] += qv1 * kv3;
            s[2][0] += qv2 * kv0; s[2][1] += qv2 * kv1; s[2][2] += qv2 * kv2; s[2][3] += qv2 * kv3;
            s[3][0] += qv3 * kv0; s[3][1] += qv3 * kv1; s[3][2] += qv3 * kv2; s[3][3] += qv3 * kv3;
        }

        // bias add + online softmax per q-row
#pragma unroll
        for (int i = 0; i < 4; i++) {
            int qi = ty4 + i;
            float rm = -1e30f;
#pragma unroll
            for (int j = 0; j < 4; j++) {
                s[i][j] += strip[(tx4 + j) - qi + 63];
                rm = fmaxf(rm, s[i][j]);
            }
#pragma unroll
            for (int off = 8; off >= 1; off >>= 1)
                rm = fmaxf(rm, __shfl_xor_sync(0xffffffffu, rm, off));
            float mn = fmaxf(m[i], rm);
            float sc = __expf(m[i] - mn);
            float rs = 0.f;
#pragma unroll
            for (int j = 0; j < 4; j++) {
                float p = __expf(s[i][j] - mn);
                s[i][j] = p;
                rs += p;
            }
#pragma unroll
            for (int off = 8; off >= 1; off >>= 1)
                rs += __shfl_xor_sync(0xffffffffu, rs, off);
            l[i] = l[i] * sc + rs;
            m[i] = mn;
#pragma unroll
            for (int j = 0; j < 4; j++) o[i][j] *= sc;
            *(float4*)&Ps[qi * 64 + tx4] = make_float4(s[i][0], s[i][1], s[i][2], s[i][3]);
        }
        __syncthreads();

        // O += P @ V  (4q x 4d per thread)
#pragma unroll 8
        for (int k = 0; k < 64; k++) {
            float4 v = *(const float4*)&Vs[k * 64 + tx4];
            float p0 = Ps[(ty4 + 0) * 64 + k];
            float p1 = Ps[(ty4 + 1) * 64 + k];
            float p2 = Ps[(ty4 + 2) * 64 + k];
            float p3 = Ps[(ty4 + 3) * 64 + k];
            o[0][0] += p0 * v.x; o[0][1] += p0 * v.y; o[0][2] += p0 * v.z; o[0][3] += p0 * v.w;
            o[1][0] += p1 * v.x; o[1][1] += p1 * v.y; o[1][2] += p1 * v.z; o[1][3] += p1 * v.w;
            o[2][0] += p2 * v.x; o[2][1] += p2 * v.y; o[2][2] += p2 * v.z; o[2][3] += p2 * v.w;
            o[3][0] += p3 * v.x; o[3][1] += p3 * v.y; o[3][2] += p3 * v.z; o[3][3] += p3 * v.w;
        }
        __syncthreads();
    }

    // epilogue: write normalized context rows
#pragma unroll
    for (int i = 0; i < 4; i++) {
        float inv = 1.f / l[i];
        int sr = q0 + ty4 + i;
        float4 r = make_float4(o[i][0] * inv, o[i][1] * inv, o[i][2] * inv, o[i][3] * inv);
        *(float4*)&g_ctx[((size_t)(b * SS + sr)) * DM + h * DK + tx4] = r;
    }
}

// ---------------- kernel 5: output projection GEMM ----------------
__global__ __launch_bounds__(256) void out_gemm(const float* __restrict__ Wo,
                                                float* __restrict__ out) {
    __shared__ float As[16][64];
    __shared__ float Bs[16][64];
    int t = threadIdx.x;
    int tx = t & 15, ty = t >> 4;
    int m0 = blockIdx.x * 64;
    int n0 = blockIdx.y * 64;

    float acc[4][4];
#pragma unroll
    for (int i = 0; i < 4; i++)
#pragma unroll
        for (int j = 0; j < 4; j++) acc[i][j] = 0.f;

    int ar = t >> 2, ac = (t & 3) * 4;
    int br = t >> 4, bc = (t & 15) * 4;

    for (int k0 = 0; k0 < DM; k0 += 16) {
        float4 av = *(const float4*)&g_ctx[(size_t)(m0 + ar) * DM + k0 + ac];
        As[ac + 0][ar] = av.x;
        As[ac + 1][ar] = av.y;
        As[ac + 2][ar] = av.z;
        As[ac + 3][ar] = av.w;
        *(float4*)&Bs[br][bc] = *(const float4*)&Wo[(size_t)(k0 + br) * DM + n0 + bc];
        __syncthreads();
#pragma unroll
        for (int kk = 0; kk < 16; kk++) {
            float4 a = *(const float4*)&As[kk][ty * 4];
            float4 b = *(const float4*)&Bs[kk][tx * 4];
            acc[0][0] += a.x * b.x; acc[0][1] += a.x * b.y; acc[0][2] += a.x * b.z; acc[0][3] += a.x * b.w;
            acc[1][0] += a.y * b.x; acc[1][1] += a.y * b.y; acc[1][2] += a.y * b.z; acc[1][3] += a.y * b.w;
            acc[2][0] += a.z * b.x; acc[2][1] += a.z * b.y; acc[2][2] += a.z * b.z; acc[2][3] += a.z * b.w;
            acc[3][0] += a.w * b.x; acc[3][1] += a.w * b.y; acc[3][2] += a.w * b.z; acc[3][3] += a.w * b.w;
        }
        __syncthreads();
    }

#pragma unroll
    for (int i = 0; i < 4; i++) {
        float4 o = make_float4(acc[i][0], acc[i][1], acc[i][2], acc[i][3]);
        *(float4*)&out[(size_t)(m0 + ty * 4 + i) * DM + n0 + tx * 4] = o;
    }
}

// ---------------- launch ----------------
extern "C" void kernel_launch(void* const* d_in, const int* in_sizes, int n_in,
                              void* d_out, int out_size) {
    const float* hs  = (const float*)d_in[0];
    const float* Wq  = (const float*)d_in[1];
    const float* Wk  = (const float*)d_in[2];
    const float* Wv  = (const float*)d_in[3];
    const float* Wo  = (const float*)d_in[4];
    const float* emb = (const float*)d_in[5];

    float* out = (float*)d_out;
    float* outb = out + (size_t)BB * SS * DM;   // position_bias region

    cudaFuncSetAttribute((const void*)attn_kernel,
                         cudaFuncAttributeMaxDynamicSharedMemorySize,
                         SM_FLOATS * sizeof(float));

    bias_tab_kernel<<<(HH * 4095 + 255) / 256, 256>>>(emb);
    bias_write_kernel<<<dim3(SS / 1024, SS, HH), 256>>>(outb);
    qkv_gemm<<<dim3((BB * SS) / 64, 24), 256>>>(hs, Wq, Wk, Wv);
    attn_kernel<<<dim3(SS / 64, HH, BB), 256, SM_FLOATS * sizeof(float)>>>();
    out_gemm<<<dim3((BB * SS) / 64, DM / 64), 256>>>(Wo, out);
}

// round 8
// speedup vs baseline: 1.8750x; 1.8750x over previous
#include <cuda_runtime.h>
#include <cuda_bf16.h>
#include <cstdint>

#define BB 2
#define SS 2048
#define DM 512
#define HH 8
#define DK 64

// ---------------- scratch (device globals; no allocation) ----------------
__device__ __nv_bfloat16 g_Qh[BB * HH * SS * DK];
__device__ __nv_bfloat16 g_Ql[BB * HH * SS * DK];
__device__ __nv_bfloat16 g_Kh[BB * HH * SS * DK];
__device__ __nv_bfloat16 g_Kl[BB * HH * SS * DK];
__device__ __nv_bfloat16 g_Vh[BB * HH * SS * DK];
__device__ __nv_bfloat16 g_Vl[BB * HH * SS * DK];
__device__ float g_ctx[BB * SS * DM];      // [b*s][h*64+d]
__device__ float g_tab[HH * 4095];         // bias value per (head, delta+2047)

// Exact integer bucketization (bidirectional T5, NUM_BUCKETS=32, MAX_DISTANCE=128).
__device__ __forceinline__ int bucket_abs(int n) {
    if (n < 8)  return n;
    if (n < 12) return 8;
    if (n < 16) return 9;
    if (n < 23) return 10;
    if (n < 32) return 11;
    if (n < 46) return 12;
    if (n < 64) return 13;
    if (n < 91) return 14;
    return 15;
}

// ---------------- kernel 1: bias table ----------------
__global__ void bias_tab_kernel(const float* __restrict__ emb) {
    int i = blockIdx.x * blockDim.x + threadIdx.x;
    if (i >= HH * 4095) return;
    int h = i / 4095;
    int didx = i - h * 4095;
    int d = didx - 2047;
    int n = d < 0 ? -d : d;
    int bkt = bucket_abs(n) + (d > 0 ? 16 : 0);
    g_tab[h * 4095 + didx] = emb[bkt * HH + h];
}

// ---------------- kernel 2: stream position_bias to output ----------------
__global__ void bias_write_kernel(float* __restrict__ outb) {
    int h = blockIdx.z;
    int q = blockIdx.y;
    int k = (blockIdx.x * 256 + threadIdx.x) * 4;
    const float* t = &g_tab[h * 4095 + (k - q + 2047)];
    float4 v = make_float4(t[0], t[1], t[2], t[3]);
    *(float4*)&outb[((size_t)h * SS + q) * SS + k] = v;
}

// ---------------- helpers ----------------
__device__ __forceinline__ uint32_t packbf(float lo, float hi) {
    uint32_t r;
    asm("cvt.rn.bf16x2.f32 %0, %1, %2;" : "=r"(r) : "f"(hi), "f"(lo));
    return r;
}
__device__ __forceinline__ float blo(uint32_t u) { return __uint_as_float(u << 16); }
__device__ __forceinline__ float bhi(uint32_t u) { return __uint_as_float(u & 0xffff0000u); }

__device__ __forceinline__ void ldsm4(uint32_t a, uint32_t& r0, uint32_t& r1, uint32_t& r2, uint32_t& r3) {
    asm volatile("ldmatrix.sync.aligned.m8n8.x4.shared.b16 {%0,%1,%2,%3}, [%4];"
                 : "=r"(r0), "=r"(r1), "=r"(r2), "=r"(r3) : "r"(a));
}
__device__ __forceinline__ void ldsm4t(uint32_t a, uint32_t& r0, uint32_t& r1, uint32_t& r2, uint32_t& r3) {
    asm volatile("ldmatrix.sync.aligned.m8n8.x4.trans.shared.b16 {%0,%1,%2,%3}, [%4];"
                 : "=r"(r0), "=r"(r1), "=r"(r2), "=r"(r3) : "r"(a));
}
__device__ __forceinline__ void mma16816(float& c0, float& c1, float& c2, float& c3,
                                         uint32_t a0, uint32_t a1, uint32_t a2, uint32_t a3,
                                         uint32_t b0, uint32_t b1) {
    asm volatile("mma.sync.aligned.m16n8k16.row.col.f32.bf16.bf16.f32 "
                 "{%0,%1,%2,%3},{%4,%5,%6,%7},{%8,%9},{%0,%1,%2,%3};"
                 : "+f"(c0), "+f"(c1), "+f"(c2), "+f"(c3)
                 : "r"(a0), "r"(a1), "r"(a2), "r"(a3), "r"(b0), "r"(b1));
}

// ---------------- kernel 3: fused QKV projection GEMM (bf16 hi/lo epilogue) ----------------
__global__ __launch_bounds__(256) void qkv_gemm(const float* __restrict__ Xh,
                                                const float* __restrict__ Wq,
                                                const float* __restrict__ Wk,
                                                const float* __restrict__ Wv) {
    __shared__ float As[16][64];
    __shared__ float Bs[16][64];
    int t = threadIdx.x;
    int tx = t & 15, ty = t >> 4;
    int m0 = blockIdx.x * 64;
    int w = blockIdx.y >> 3;           // 0=Q,1=K,2=V
    int h = blockIdx.y & 7;
    const float* Bm = (w == 0) ? Wq : ((w == 1) ? Wk : Wv);
    __nv_bfloat16* dh = (w == 0) ? g_Qh : ((w == 1) ? g_Kh : g_Vh);
    __nv_bfloat16* dl = (w == 0) ? g_Ql : ((w == 1) ? g_Kl : g_Vl);
    int n0 = h * 64;

    float acc[4][4];
#pragma unroll
    for (int i = 0; i < 4; i++)
#pragma unroll
        for (int j = 0; j < 4; j++) acc[i][j] = 0.f;

    int ar = t >> 2, ac = (t & 3) * 4;
    int br = t >> 4, bc = (t & 15) * 4;

    for (int k0 = 0; k0 < DM; k0 += 16) {
        float4 av = *(const float4*)&Xh[(size_t)(m0 + ar) * DM + k0 + ac];
        As[ac + 0][ar] = av.x;
        As[ac + 1][ar] = av.y;
        As[ac + 2][ar] = av.z;
        As[ac + 3][ar] = av.w;
        *(float4*)&Bs[br][bc] = *(const float4*)&Bm[(size_t)(k0 + br) * (HH * DK) + n0 + bc];
        __syncthreads();
#pragma unroll
        for (int kk = 0; kk < 16; kk++) {
            float4 a = *(const float4*)&As[kk][ty * 4];
            float4 b = *(const float4*)&Bs[kk][tx * 4];
            acc[0][0] += a.x * b.x; acc[0][1] += a.x * b.y; acc[0][2] += a.x * b.z; acc[0][3] += a.x * b.w;
            acc[1][0] += a.y * b.x; acc[1][1] += a.y * b.y; acc[1][2] += a.y * b.z; acc[1][3] += a.y * b.w;
            acc[2][0] += a.z * b.x; acc[2][1] += a.z * b.y; acc[2][2] += a.z * b.z; acc[2][3] += a.z * b.w;
            acc[3][0] += a.w * b.x; acc[3][1] += a.w * b.y; acc[3][2] += a.w * b.z; acc[3][3] += a.w * b.w;
        }
        __syncthreads();
    }

    int b = m0 >> 11;
    int s0 = m0 & 2047;
#pragma unroll
    for (int i = 0; i < 4; i++) {
        int sr = s0 + ty * 4 + i;
        size_t base = (((size_t)(b * HH + h)) * SS + sr) * DK + tx * 4;
        float vx = acc[i][0], vy = acc[i][1], vz = acc[i][2], vw = acc[i][3];
        uint32_t h01 = packbf(vx, vy), h23 = packbf(vz, vw);
        uint32_t l01 = packbf(vx - blo(h01), vy - bhi(h01));
        uint32_t l23 = packbf(vz - blo(h23), vw - bhi(h23));
        *(uint2*)&dh[base] = make_uint2(h01, h23);
        *(uint2*)&dl[base] = make_uint2(l01, l23);
    }
}

// ---------------- kernel 4: flash attention, bf16-split HMMA ----------------
// smem (bytes): QH 0..16K | QL 16K..32K | KH 32K.. | KL 40K.. | VH 48K.. | VL 56K.. | strip 64K
#define SQH 0
#define SQL 16384
#define SKH 32768
#define SKL 40960
#define SVH 49152
#define SVL 57344
#define SSTRIP 65536
#define SM_BYTES (65536 + 768)

__global__ __launch_bounds__(256) void attn_kernel() {
    extern __shared__ char smc[];
    uint32_t smb = (uint32_t)__cvta_generic_to_shared(smc);
    float* stripf = (float*)(smc + SSTRIP);

    const int t = threadIdx.x;
    const int w = t >> 5, lane = t & 31;
    const int tile = lane >> 3, rowin = lane & 7;
    const int g = lane >> 2, q4 = lane & 3;
    const int q0 = blockIdx.x * 128;
    const int h = blockIdx.y, b = blockIdx.z;

    size_t off = ((size_t)(b * HH + h)) * SS * DK;
    const __nv_bfloat16* Qhg = g_Qh + off + (size_t)q0 * DK;
    const __nv_bfloat16* Qlg = g_Ql + off + (size_t)q0 * DK;
    const __nv_bfloat16* Khg = g_Kh + off;
    const __nv_bfloat16* Klg = g_Kl + off;
    const __nv_bfloat16* Vhg = g_Vh + off;
    const __nv_bfloat16* Vlg = g_Vl + off;

    // stage Q hi/lo [128][64] bf16, XOR-swizzled (16B chunks)
#pragma unroll
    for (int i = 0; i < 8; i++) {
        int id = t + i * 256;
        int plane = i >> 2;                // 0=hi, 1=lo (exact: id/1024)
        int rid = id & 1023;
        int row = rid >> 3, c = rid & 7;
        const __nv_bfloat16* src = (plane ? Qlg : Qhg) + row * 64 + c * 8;
        uint32_t d = (plane ? SQL : SQH) + row * 128 + (((c ^ (row & 7))) << 4);
        *(uint4*)(smc + d) = *(const uint4*)src;
    }
    __syncthreads();

    // Q A-fragments, register resident: qh[kc][0..3], ql[kc][0..3]
    uint32_t qh[4][4], ql[4][4];
#pragma unroll
    for (int kc = 0; kc < 4; kc++) {
        int row = 16 * w + ((tile & 1) << 3) + rowin;
        int ch = 2 * kc + (tile >> 1);
        uint32_t sw = row * 128 + ((ch ^ (row & 7)) << 4);
        ldsm4(smb + SQH + sw, qh[kc][0], qh[kc][1], qh[kc][2], qh[kc][3]);
        ldsm4(smb + SQL + sw, ql[kc][0], ql[kc][1], ql[kc][2], ql[kc][3]);
    }

    float s[32], o[32];
    float m0 = -1e30f, m1 = -1e30f, l0 = 0.f, l1 = 0.f;
#pragma unroll
    for (int i = 0; i < 32; i++) o[i] = 0.f;

    for (int kt = 0; kt < SS / 64; kt++) {
        const int k0 = kt * 64;
        // stage K/V hi/lo tiles [64][64] bf16 swizzled
#pragma unroll
        for (int i = 0; i < 8; i++) {
            const int plane = i >> 1;      // 0=Kh 1=Kl 2=Vh 3=Vl (exact: id/512)
            int rid = ((i & 1) << 8) + t;
            int row = rid >> 3, c = rid & 7;
            const __nv_bfloat16* src =
                (plane == 0 ? Khg : plane == 1 ? Klg : plane == 2 ? Vhg : Vlg)
                + (size_t)(k0 + row) * 64 + c * 8;
            uint32_t d = SKH + plane * 8192 + row * 128 + ((c ^ (row & 7)) << 4);
            *(uint4*)(smc + d) = *(const uint4*)src;
        }
        if (t < 191) stripf[t] = g_tab[h * 4095 + 2047 + k0 - q0 - 127 + t];
        __syncthreads();

        // ---- S = Q K^T (hi*hi + hi*lo + lo*hi) ----
#pragma unroll
        for (int i = 0; i < 32; i++) s[i] = 0.f;
#pragma unroll
        for (int kc = 0; kc < 4; kc++) {
            uint32_t kh[16], kl[16];
#pragma unroll
            for (int j = 0; j < 4; j++) {
                int key = 16 * j + ((tile >> 1) << 3) + rowin;
                int ch = 2 * kc + (tile & 1);
                uint32_t sw = key * 128 + ((ch ^ (key & 7)) << 4);
                ldsm4(smb + SKH + sw, kh[4 * j + 0], kh[4 * j + 1], kh[4 * j + 2], kh[4 * j + 3]);
                ldsm4(smb + SKL + sw, kl[4 * j + 0], kl[4 * j + 1], kl[4 * j + 2], kl[4 * j + 3]);
            }
#pragma unroll
            for (int nc = 0; nc < 8; nc++) {
                mma16816(s[4 * nc], s[4 * nc + 1], s[4 * nc + 2], s[4 * nc + 3],
                         qh[kc][0], qh[kc][1], qh[kc][2], qh[kc][3], kh[2 * nc], kh[2 * nc + 1]);
                mma16816(s[4 * nc], s[4 * nc + 1], s[4 * nc + 2], s[4 * nc + 3],
                         qh[kc][0], qh[kc][1], qh[kc][2], qh[kc][3], kl[2 * nc], kl[2 * nc + 1]);
                mma16816(s[4 * nc], s[4 * nc + 1], s[4 * nc + 2], s[4 * nc + 3],
                         ql[kc][0], ql[kc][1], ql[kc][2], ql[kc][3], kh[2 * nc], kh[2 * nc + 1]);
            }
        }

        // ---- bias add + online softmax (per-warp rows: g and g+8 of 16-row stripe) ----
        {
            int rb = 16 * w + g;
#pragma unroll
            for (int nc = 0; nc < 8; nc++) {
                int i0 = 8 * nc + 2 * q4 - rb + 127;
                s[4 * nc + 0] += stripf[i0];
                s[4 * nc + 1] += stripf[i0 + 1];
                s[4 * nc + 2] += stripf[i0 - 8];
                s[4 * nc + 3] += stripf[i0 - 7];
            }
        }
        float mx0 = -1e30f, mx1 = -1e30f;
#pragma unroll
        for (int nc = 0; nc < 8; nc++) {
            mx0 = fmaxf(mx0, fmaxf(s[4 * nc + 0], s[4 * nc + 1]));
            mx1 = fmaxf(mx1, fmaxf(s[4 * nc + 2], s[4 * nc + 3]));
        }
        mx0 = fmaxf(mx0, __shfl_xor_sync(0xffffffffu, mx0, 1));
        mx0 = fmaxf(mx0, __shfl_xor_sync(0xffffffffu, mx0, 2));
        mx1 = fmaxf(mx1, __shfl_xor_sync(0xffffffffu, mx1, 1));
        mx1 = fmaxf(mx1, __shfl_xor_sync(0xffffffffu, mx1, 2));
        float mn0 = fmaxf(m0, mx0), mn1 = fmaxf(m1, mx1);
        float sc0 = __expf(m0 - mn0), sc1 = __expf(m1 - mn1);
        m0 = mn0; m1 = mn1;
        float su0 = 0.f, su1 = 0.f;
#pragma unroll
        for (int nc = 0; nc < 8; nc++) {
            s[4 * nc + 0] = __expf(s[4 * nc + 0] - mn0); su0 += s[4 * nc + 0];
            s[4 * nc + 1] = __expf(s[4 * nc + 1] - mn0); su0 += s[4 * nc + 1];
            s[4 * nc + 2] = __expf(s[4 * nc + 2] - mn1); su1 += s[4 * nc + 2];
            s[4 * nc + 3] = __expf(s[4 * nc + 3] - mn1); su1 += s[4 * nc + 3];
        }
        su0 += __shfl_xor_sync(0xffffffffu, su0, 1);
        su0 += __shfl_xor_sync(0xffffffffu, su0, 2);
        su1 += __shfl_xor_sync(0xffffffffu, su1, 1);
        su1 += __shfl_xor_sync(0xffffffffu, su1, 2);
        l0 = l0 * sc0 + su0;
        l1 = l1 * sc1 + su1;
#pragma unroll
        for (int nd = 0; nd < 8; nd++) {
            o[4 * nd + 0] *= sc0; o[4 * nd + 1] *= sc0;
            o[4 * nd + 2] *= sc1; o[4 * nd + 3] *= sc1;
        }

        // ---- O += P V (hi*hi + hi*lo + lo*hi) ----
#pragma unroll
        for (int ko = 0; ko < 4; ko++) {
            int na = 8 * ko;
            uint32_t ph0 = packbf(s[na + 0], s[na + 1]);
            uint32_t ph1 = packbf(s[na + 2], s[na + 3]);
            uint32_t ph2 = packbf(s[na + 4], s[na + 5]);
            uint32_t ph3 = packbf(s[na + 6], s[na + 7]);
            uint32_t pl0 = packbf(s[na + 0] - blo(ph0), s[na + 1] - bhi(ph0));
            uint32_t pl1 = packbf(s[na + 2] - blo(ph1), s[na + 3] - bhi(ph1));
            uint32_t pl2 = packbf(s[na + 4] - blo(ph2), s[na + 5] - bhi(ph2));
            uint32_t pl3 = packbf(s[na + 6] - blo(ph3), s[na + 7] - bhi(ph3));
            uint32_t vh[16], vl[16];
#pragma unroll
            for (int jj = 0; jj < 4; jj++) {
                int key = 16 * ko + ((tile & 1) << 3) + rowin;
                int ch = 2 * jj + (tile >> 1);
                uint32_t sw = key * 128 + ((ch ^ (key & 7)) << 4);
                ldsm4t(smb + SVH + sw, vh[4 * jj + 0], vh[4 * jj + 1], vh[4 * jj + 2], vh[4 * jj + 3]);
                ldsm4t(smb + SVL + sw, vl[4 * jj + 0], vl[4 * jj + 1], vl[4 * jj + 2], vl[4 * jj + 3]);
            }
#pragma unroll
            for (int nd = 0; nd < 8; nd++) {
                mma16816(o[4 * nd], o[4 * nd + 1], o[4 * nd + 2], o[4 * nd + 3],
                         ph0, ph1, ph2, ph3, vh[2 * nd], vh[2 * nd + 1]);
                mma16816(o[4 * nd], o[4 * nd + 1], o[4 * nd + 2], o[4 * nd + 3],
                         ph0, ph1, ph2, ph3, vl[2 * nd], vl[2 * nd + 1]);
                mma16816(o[4 * nd], o[4 * nd + 1], o[4 * nd + 2], o[4 * nd + 3],
                         pl0, pl1, pl2, pl3, vh[2 * nd], vh[2 * nd + 1]);
            }
        }
        __syncthreads();
    }

    // normalize + write context
    float i0 = 1.f / l0, i1 = 1.f / l1;
    int r0g = q0 + 16 * w + g;
    float* C0 = g_ctx + ((size_t)(b * SS + r0g)) * DM + h * DK;
    float* C1 = g_ctx + ((size_t)(b * SS + r0g + 8)) * DM + h * DK;
#pragma unroll
    for (int nd = 0; nd < 8; nd++) {
        int d = 8 * nd + 2 * q4;
        *(float2*)&C0[d] = make_float2(o[4 * nd + 0] * i0, o[4 * nd + 1] * i0);
        *(float2*)&C1[d] = make_float2(o[4 * nd + 2] * i1, o[4 * nd + 3] * i1);
    }
}

// ---------------- kernel 5: output projection GEMM ----------------
__global__ __launch_bounds__(256) void out_gemm(const float* __restrict__ Wo,
                                                float* __restrict__ out) {
    __shared__ float As[16][64];
    __shared__ float Bs[16][64];
    int t = threadIdx.x;
    int tx = t & 15, ty = t >> 4;
    int m0 = blockIdx.x * 64;
    int n0 = blockIdx.y * 64;

    float acc[4][4];
#pragma unroll
    for (int i = 0; i < 4; i++)
#pragma unroll
        for (int j = 0; j < 4; j++) acc[i][j] = 0.f;

    int ar = t >> 2, ac = (t & 3) * 4;
    int br = t >> 4, bc = (t & 15) * 4;

    for (int k0 = 0; k0 < DM; k0 += 16) {
        float4 av = *(const float4*)&g_ctx[(size_t)(m0 + ar) * DM + k0 + ac];
        As[ac + 0][ar] = av.x;
        As[ac + 1][ar] = av.y;
        As[ac + 2][ar] = av.z;
        As[ac + 3][ar] = av.w;
        *(float4*)&Bs[br][bc] = *(const float4*)&Wo[(size_t)(k0 + br) * DM + n0 + bc];
        __syncthreads();
#pragma unroll
        for (int kk = 0; kk < 16; kk++) {
            float4 a = *(const float4*)&As[kk][ty * 4];
            float4 b = *(const float4*)&Bs[kk][tx * 4];
            acc[0][0] += a.x * b.x; acc[0][1] += a.x * b.y; acc[0][2] += a.x * b.z; acc[0][3] += a.x * b.w;
            acc[1][0] += a.y * b.x; acc[1][1] += a.y * b.y; acc[1][2] += a.y * b.z; acc[1][3] += a.y * b.w;
            acc[2][0] += a.z * b.x; acc[2][1] += a.z * b.y; acc[2][2] += a.z * b.z; acc[2][3] += a.z * b.w;
            acc[3][0] += a.w * b.x; acc[3][1] += a.w * b.y; acc[3][2] += a.w * b.z; acc[3][3] += a.w * b.w;
        }
        __syncthreads();
    }

#pragma unroll
    for (int i = 0; i < 4; i++) {
        float4 o = make_float4(acc[i][0], acc[i][1], acc[i][2], acc[i][3]);
        *(float4*)&out[(size_t)(m0 + ty * 4 + i) * DM + n0 + tx * 4] = o;
    }
}

// ---------------- launch ----------------
extern "C" void kernel_launch(void* const* d_in, const int* in_sizes, int n_in,
                              void* d_out, int out_size) {
    const float* hs  = (const float*)d_in[0];
    const float* Wq  = (const float*)d_in[1];
    const float* Wk  = (const float*)d_in[2];
    const float* Wv  = (const float*)d_in[3];
    const float* Wo  = (const float*)d_in[4];
    const float* emb = (const float*)d_in[5];

    float* out = (float*)d_out;
    float* outb = out + (size_t)BB * SS * DM;

    cudaFuncSetAttribute((const void*)attn_kernel,
                         cudaFuncAttributeMaxDynamicSharedMemorySize, SM_BYTES);

    bias_tab_kernel<<<(HH * 4095 + 255) / 256, 256>>>(emb);
    bias_write_kernel<<<dim3(SS / 1024, SS, HH), 256>>>(outb);
    qkv_gemm<<<dim3((BB * SS) / 64, 24), 256>>>(hs, Wq, Wk, Wv);
    attn_kernel<<<dim3(SS / 128, HH, BB), 256, SM_BYTES>>>();
    out_gemm<<<dim3((BB * SS) / 64, DM / 64), 256>>>(Wo, out);
}